// round 7
// baseline (speedup 1.0000x reference)
#include <cuda_runtime.h>
#include <cstddef>

#define BB 32
#define TT 512
#define DD 512
#define MAXLEN 2048
#define ROWS_PER_BLOCK 8

// scratch (device globals — no allocation allowed)
__device__ int g_csum[BB * TT];
__device__ int g_dursum[BB];

// Kernel 1: per-batch inclusive scan of duration; also writes mel_lengths tail.
__global__ void scan_kernel(const int* __restrict__ dur,
                            float* __restrict__ out, int tail) {
    __shared__ int s[TT];
    const int b = blockIdx.x;
    const int tid = threadIdx.x;
    s[tid] = dur[b * TT + tid];
    __syncthreads();
    // Hillis–Steele inclusive scan over 512 elements (9 steps)
    #pragma unroll
    for (int off = 1; off < TT; off <<= 1) {
        int add = (tid >= off) ? s[tid - off] : 0;
        __syncthreads();
        s[tid] += add;
        __syncthreads();
    }
    g_csum[b * TT + tid] = s[tid];
    if (tid == TT - 1) {
        int ds = s[tid];
        g_dursum[b] = ds;
        // mel_lengths = max(dur_sum, 1), stored as float in the concat tail
        out[tail + b] = (float)(ds > 0 ? ds : 1);
    }
}

// Kernel 2: each block = 8 output frames of one batch. Warp w owns frame
// t = blockIdx.x*8 + w: binary-search csum in smem (searchsorted right),
// then copy (or zero) one 512-float row as 128 float4.
__global__ void __launch_bounds__(256)
regulate_kernel(const float4* __restrict__ x, float4* __restrict__ out) {
    __shared__ int s_csum[TT];
    __shared__ int s_ds;
    const int b = blockIdx.y;
    const int tid = threadIdx.x;

    for (int i = tid; i < TT; i += 256) s_csum[i] = g_csum[b * TT + i];
    if (tid == 0) s_ds = g_dursum[b];
    __syncthreads();

    const int warp = tid >> 5;
    const int lane = tid & 31;
    const int t = blockIdx.x * ROWS_PER_BLOCK + warp;

    float4* orow = out + ((size_t)b * MAXLEN + t) * (DD / 4);

    if (t >= s_ds) {
        // zero padding (output buffer is poisoned, must write zeros)
        const float4 z = make_float4(0.f, 0.f, 0.f, 0.f);
        #pragma unroll
        for (int k = 0; k < 4; k++) orow[lane + 32 * k] = z;
    } else {
        // searchsorted right: first j with csum[j] > t
        int lo = 0, hi = TT;
        while (lo < hi) {
            int mid = (lo + hi) >> 1;
            if (s_csum[mid] > t) hi = mid; else lo = mid + 1;
        }
        int idx = lo < (TT - 1) ? lo : (TT - 1);  // clip (matches reference)
        const float4* xrow = x + ((size_t)b * TT + idx) * (DD / 4);
        #pragma unroll
        for (int k = 0; k < 4; k++) orow[lane + 32 * k] = xrow[lane + 32 * k];
    }
}

extern "C" void kernel_launch(void* const* d_in, const int* in_sizes, int n_in,
                              void* d_out, int out_size) {
    const float* x   = (const float*)d_in[0];   // [32,512,512] f32
    const int*   dur = (const int*)d_in[1];     // [32,512] i32
    float* out = (float*)d_out;                 // [32*2048*512 + 32] f32

    const int tail = out_size - BB;  // mel_lengths live at the end

    scan_kernel<<<BB, TT>>>(dur, out, tail);

    dim3 grid(MAXLEN / ROWS_PER_BLOCK, BB);
    regulate_kernel<<<grid, 256>>>((const float4*)x, (float4*)out);
}

// round 10
// speedup vs baseline: 1.1405x; 1.1405x over previous
#include <cuda_runtime.h>
#include <cstddef>

#define BB 32
#define TT 512
#define DD 512
#define MAXLEN 2048
#define ROWS_PER_WARP 2
#define WARPS_PER_BLOCK 8
#define ROWS_PER_BLOCK (ROWS_PER_WARP * WARPS_PER_BLOCK)   // 16

// scratch (device globals — no allocation allowed)
__device__ int g_idx[BB * MAXLEN];   // frame -> phoneme index, -1 = padding

// Kernel 1: per-batch scan of duration + expansion into g_idx + mel_lengths tail.
__global__ void __launch_bounds__(TT)
scan_expand_kernel(const int* __restrict__ dur,
                   float* __restrict__ out, int tail) {
    __shared__ int s[TT];
    const int b = blockIdx.x;
    const int tid = threadIdx.x;
    s[tid] = dur[b * TT + tid];
    __syncthreads();
    // Hillis–Steele inclusive scan over 512 elements (9 steps)
    #pragma unroll
    for (int off = 1; off < TT; off <<= 1) {
        int add = (tid >= off) ? s[tid - off] : 0;
        __syncthreads();
        s[tid] += add;
        __syncthreads();
    }
    // expand: frames [csum[j-1], csum[j]) belong to phoneme j (truncate at MAXLEN)
    int start = (tid == 0) ? 0 : s[tid - 1];
    int end   = s[tid];
    if (start > MAXLEN) start = MAXLEN;
    if (end   > MAXLEN) end   = MAXLEN;
    int* row = g_idx + b * MAXLEN;
    for (int t = start; t < end; t++) row[t] = tid;

    // padding fill: frames [min(ds,MAXLEN), MAXLEN) -> -1
    const int ds = s[TT - 1];
    int ds_c = ds > MAXLEN ? MAXLEN : ds;
    for (int t = ds_c + tid; t < MAXLEN; t += TT) row[t] = -1;

    if (tid == 0) {
        // mel_lengths = max(dur_sum, 1), stored as float in the concat tail
        out[tail + b] = (float)(ds > 0 ? ds : 1);
    }
}

// Kernel 2: pure copy engine. Each warp owns ROWS_PER_WARP output frames:
// read idx (broadcast), always load a source row (row 0 if padding — L1-hot),
// select zero in registers, stream-store 2KB as 4x st.128 per row.
__global__ void __launch_bounds__(256)
regulate_kernel(const float4* __restrict__ x, float4* __restrict__ out) {
    const int b = blockIdx.y;
    const int warp = threadIdx.x >> 5;
    const int lane = threadIdx.x & 31;
    const int t0 = blockIdx.x * ROWS_PER_BLOCK + warp * ROWS_PER_WARP;

    // broadcast idx loads (2 independent)
    int i0 = __ldg(&g_idx[b * MAXLEN + t0]);
    int i1 = __ldg(&g_idx[b * MAXLEN + t0 + 1]);

    const size_t xbase = (size_t)b * TT * (DD / 4);
    const float4* xr0 = x + xbase + (size_t)(i0 < 0 ? 0 : i0) * (DD / 4) + lane;
    const float4* xr1 = x + xbase + (size_t)(i1 < 0 ? 0 : i1) * (DD / 4) + lane;

    // 8 independent 16B loads (MLP=8)
    float4 v0[4], v1[4];
    #pragma unroll
    for (int k = 0; k < 4; k++) v0[k] = __ldg(xr0 + 32 * k);
    #pragma unroll
    for (int k = 0; k < 4; k++) v1[k] = __ldg(xr1 + 32 * k);

    const float4 z = make_float4(0.f, 0.f, 0.f, 0.f);
    if (i0 < 0) {
        #pragma unroll
        for (int k = 0; k < 4; k++) v0[k] = z;
    }
    if (i1 < 0) {
        #pragma unroll
        for (int k = 0; k < 4; k++) v1[k] = z;
    }

    float4* o0 = out + ((size_t)b * MAXLEN + t0) * (DD / 4) + lane;
    float4* o1 = o0 + (DD / 4);
    // streaming stores: don't let the 128MB write stream evict x from L2
    #pragma unroll
    for (int k = 0; k < 4; k++) __stcs(o0 + 32 * k, v0[k]);
    #pragma unroll
    for (int k = 0; k < 4; k++) __stcs(o1 + 32 * k, v1[k]);
}

extern "C" void kernel_launch(void* const* d_in, const int* in_sizes, int n_in,
                              void* d_out, int out_size) {
    const float* x   = (const float*)d_in[0];   // [32,512,512] f32
    const int*   dur = (const int*)d_in[1];     // [32,512] i32
    float* out = (float*)d_out;                 // [32*2048*512 + 32] f32

    const int tail = out_size - BB;  // mel_lengths live at the end

    scan_expand_kernel<<<BB, TT>>>(dur, out, tail);

    dim3 grid(MAXLEN / ROWS_PER_BLOCK, BB);
    regulate_kernel<<<grid, 256>>>((const float4*)x, (float4*)out);
}

// round 12
// speedup vs baseline: 1.2318x; 1.0800x over previous
#include <cuda_runtime.h>
#include <cstddef>

#define BB 32
#define TT 512
#define DD 512
#define MAXLEN 2048
#define ROWS_PER_WARP 2
#define WARPS_PER_BLOCK 8
#define ROWS_PER_BLOCK (ROWS_PER_WARP * WARPS_PER_BLOCK)   // 16

// scratch (device globals — no allocation allowed)
__device__ int g_idx[BB * MAXLEN];   // frame -> phoneme index, -1 = padding

// Kernel 1: per-batch scan (shuffle-based, 2 barriers) + expansion into g_idx
// + mel_lengths tail.
__global__ void __launch_bounds__(TT)
scan_expand_kernel(const int* __restrict__ dur,
                   float* __restrict__ out, int tail) {
    __shared__ int wsum[TT / 32];          // 16 warp totals
    const int b   = blockIdx.x;
    const int tid = threadIdx.x;
    const int lane = tid & 31;
    const int wid  = tid >> 5;

    const int d = dur[b * TT + tid];

    // warp inclusive scan
    int v = d;
    #pragma unroll
    for (int o = 1; o < 32; o <<= 1) {
        int n = __shfl_up_sync(0xffffffffu, v, o);
        if (lane >= o) v += n;
    }
    if (lane == 31) wsum[wid] = v;
    __syncthreads();

    // scan the 16 warp totals (first 16 threads)
    if (tid < 16) {
        int w = wsum[tid];
        #pragma unroll
        for (int o = 1; o < 16; o <<= 1) {
            int n = __shfl_up_sync(0x0000ffffu, w, o);
            if (tid >= o) w += n;
        }
        wsum[tid] = w;
    }
    __syncthreads();

    const int base  = wid ? wsum[wid - 1] : 0;
    const int end_i = base + v;          // inclusive csum at tid
    const int ds    = wsum[15];          // total duration

    // expand: frames [end_i - d, end_i) belong to phoneme tid (truncate)
    int start = end_i - d;
    int end   = end_i;
    if (start > MAXLEN) start = MAXLEN;
    if (end   > MAXLEN) end   = MAXLEN;
    int* row = g_idx + b * MAXLEN;
    for (int t = start; t < end; t++) row[t] = tid;

    // padding fill: frames [min(ds,MAXLEN), MAXLEN) -> -1
    int ds_c = ds > MAXLEN ? MAXLEN : ds;
    for (int t = ds_c + tid; t < MAXLEN; t += TT) row[t] = -1;

    if (tid == 0) {
        // mel_lengths = max(dur_sum, 1), stored as float in the concat tail
        out[tail + b] = (float)(ds > 0 ? ds : 1);
    }
}

// Kernel 2: pure copy engine. Each warp owns 2 output frames: one int2 idx
// fetch, common-case batched 8x ld.128 (MLP=8), streaming 8x st.128.
// Padding rows issue NO loads.
__global__ void __launch_bounds__(256)
regulate_kernel(const float4* __restrict__ x, float4* __restrict__ out) {
    const int b    = blockIdx.y;
    const int warp = threadIdx.x >> 5;
    const int lane = threadIdx.x & 31;
    const int t0   = blockIdx.x * ROWS_PER_BLOCK + warp * ROWS_PER_WARP;

    // one 8B broadcast load for both frame indices (t0 is even -> aligned)
    const int2 ii = __ldg((const int2*)&g_idx[b * MAXLEN + t0]);

    const size_t xbase = (size_t)b * TT * (DD / 4);
    const float4 z = make_float4(0.f, 0.f, 0.f, 0.f);
    float4 v0[4], v1[4];

    if ((ii.x | ii.y) >= 0) {
        // common case: both rows valid -> 8 independent 16B loads batched
        const float4* xr0 = x + xbase + (size_t)ii.x * (DD / 4) + lane;
        const float4* xr1 = x + xbase + (size_t)ii.y * (DD / 4) + lane;
        #pragma unroll
        for (int k = 0; k < 4; k++) v0[k] = __ldg(xr0 + 32 * k);
        #pragma unroll
        for (int k = 0; k < 4; k++) v1[k] = __ldg(xr1 + 32 * k);
    } else {
        // boundary / padding warps: load only valid rows, zero the rest
        if (ii.x >= 0) {
            const float4* xr0 = x + xbase + (size_t)ii.x * (DD / 4) + lane;
            #pragma unroll
            for (int k = 0; k < 4; k++) v0[k] = __ldg(xr0 + 32 * k);
        } else {
            #pragma unroll
            for (int k = 0; k < 4; k++) v0[k] = z;
        }
        if (ii.y >= 0) {
            const float4* xr1 = x + xbase + (size_t)ii.y * (DD / 4) + lane;
            #pragma unroll
            for (int k = 0; k < 4; k++) v1[k] = __ldg(xr1 + 32 * k);
        } else {
            #pragma unroll
            for (int k = 0; k < 4; k++) v1[k] = z;
        }
    }

    float4* o0 = out + ((size_t)b * MAXLEN + t0) * (DD / 4) + lane;
    float4* o1 = o0 + (DD / 4);
    // streaming stores: don't let the 128MB write stream evict x from L2
    #pragma unroll
    for (int k = 0; k < 4; k++) __stcs(o0 + 32 * k, v0[k]);
    #pragma unroll
    for (int k = 0; k < 4; k++) __stcs(o1 + 32 * k, v1[k]);
}

extern "C" void kernel_launch(void* const* d_in, const int* in_sizes, int n_in,
                              void* d_out, int out_size) {
    const float* x   = (const float*)d_in[0];   // [32,512,512] f32
    const int*   dur = (const int*)d_in[1];     // [32,512] i32
    float* out = (float*)d_out;                 // [32*2048*512 + 32] f32

    const int tail = out_size - BB;  // mel_lengths live at the end

    scan_expand_kernel<<<BB, TT>>>(dur, out, tail);

    dim3 grid(MAXLEN / ROWS_PER_BLOCK, BB);
    regulate_kernel<<<grid, 256>>>((const float4*)x, (float4*)out);
}

// round 14
// speedup vs baseline: 1.2405x; 1.0071x over previous
#include <cuda_runtime.h>
#include <cstddef>

#define BB 32
#define TT 512
#define DD 512
#define MAXLEN 2048
#define ROWS_PER_WARP 2
#define WARPS_PER_BLOCK 8
#define ROWS_PER_BLOCK (ROWS_PER_WARP * WARPS_PER_BLOCK)   // 16

// Fused length regulator. Each block: recompute the batch csum (2 elems/thread
// shuffle scan), lanes 0-1 of each warp binary-search their 2 output frames,
// then the copy engine streams 2KB rows (batched MLP=8 loads, st.cs stores).
__global__ void __launch_bounds__(256)
fused_regulate_kernel(const float4* __restrict__ x,
                      const int2*   __restrict__ dur2,   // duration as int2
                      float* __restrict__ out_f, int tail) {
    __shared__ int s_csum[TT];
    __shared__ int s_w[WARPS_PER_BLOCK];

    const int b    = blockIdx.y;
    const int tid  = threadIdx.x;
    const int lane = tid & 31;
    const int wid  = tid >> 5;

    // ---- prologue: inclusive scan of duration[b, 0..511], 2 elems/thread ----
    const int2 dd = __ldg(&dur2[b * (TT / 2) + tid]);
    const int pair = dd.x + dd.y;

    // warp inclusive scan of pair sums
    int v = pair;
    #pragma unroll
    for (int o = 1; o < 32; o <<= 1) {
        int n = __shfl_up_sync(0xffffffffu, v, o);
        if (lane >= o) v += n;
    }
    if (lane == 31) s_w[wid] = v;
    __syncthreads();

    // scan the 8 warp totals
    if (tid < WARPS_PER_BLOCK) {
        int w = s_w[tid];
        #pragma unroll
        for (int o = 1; o < WARPS_PER_BLOCK; o <<= 1) {
            int n = __shfl_up_sync(0x000000ffu, w, o);
            if (tid >= o) w += n;
        }
        s_w[tid] = w;
    }
    __syncthreads();

    const int base_excl = (wid ? s_w[wid - 1] : 0) + (v - pair);
    // csum[2*tid] = base + dd.x ; csum[2*tid+1] = base + dd.x + dd.y
    ((int2*)s_csum)[tid] = make_int2(base_excl + dd.x, base_excl + pair);
    const int ds = s_w[WARPS_PER_BLOCK - 1];
    __syncthreads();

    // mel_lengths tail (one thread per batch): max(dur_sum, 1) as float
    if (blockIdx.x == 0 && tid == 0)
        out_f[tail + b] = (float)(ds > 0 ? ds : 1);

    // ---- per-warp frame indices: lanes 0-1 search in parallel ----
    const int t0 = blockIdx.x * ROWS_PER_BLOCK + wid * ROWS_PER_WARP;
    int idx = -1;
    if (lane < ROWS_PER_WARP) {
        const int t = t0 + lane;
        if (t < ds) {
            // searchsorted right: first j with csum[j] > t.
            // NOTE: range-512 worst case needs 10 halving steps (not 9):
            // 512->256->128->64->32->16->8->4->2->1->0.
            int lo = 0, hi = TT;
            #pragma unroll
            for (int step = 0; step < 10; step++) {
                if (lo < hi) {
                    int mid = (lo + hi) >> 1;
                    if (s_csum[mid] > t) hi = mid; else lo = mid + 1;
                }
            }
            idx = lo < (TT - 1) ? lo : (TT - 1);
        }
    }
    const int i0 = __shfl_sync(0xffffffffu, idx, 0);
    const int i1 = __shfl_sync(0xffffffffu, idx, 1);

    // ---- copy engine ----
    const size_t xbase = (size_t)b * TT * (DD / 4);
    const float4 z = make_float4(0.f, 0.f, 0.f, 0.f);
    float4 v0[4], v1[4];

    if ((i0 | i1) >= 0) {
        // common case: both rows valid -> 8 independent 16B loads batched
        const float4* xr0 = x + xbase + (size_t)i0 * (DD / 4) + lane;
        const float4* xr1 = x + xbase + (size_t)i1 * (DD / 4) + lane;
        #pragma unroll
        for (int k = 0; k < 4; k++) v0[k] = __ldg(xr0 + 32 * k);
        #pragma unroll
        for (int k = 0; k < 4; k++) v1[k] = __ldg(xr1 + 32 * k);
    } else {
        // boundary / padding warps: load only valid rows, zero the rest
        if (i0 >= 0) {
            const float4* xr0 = x + xbase + (size_t)i0 * (DD / 4) + lane;
            #pragma unroll
            for (int k = 0; k < 4; k++) v0[k] = __ldg(xr0 + 32 * k);
        } else {
            #pragma unroll
            for (int k = 0; k < 4; k++) v0[k] = z;
        }
        if (i1 >= 0) {
            const float4* xr1 = x + xbase + (size_t)i1 * (DD / 4) + lane;
            #pragma unroll
            for (int k = 0; k < 4; k++) v1[k] = __ldg(xr1 + 32 * k);
        } else {
            #pragma unroll
            for (int k = 0; k < 4; k++) v1[k] = z;
        }
    }

    float4* o0 = (float4*)out_f + ((size_t)b * MAXLEN + t0) * (DD / 4) + lane;
    float4* o1 = o0 + (DD / 4);
    // streaming stores: don't let the 128MB write stream evict x from L2
    #pragma unroll
    for (int k = 0; k < 4; k++) __stcs(o0 + 32 * k, v0[k]);
    #pragma unroll
    for (int k = 0; k < 4; k++) __stcs(o1 + 32 * k, v1[k]);
}

extern "C" void kernel_launch(void* const* d_in, const int* in_sizes, int n_in,
                              void* d_out, int out_size) {
    const float* x   = (const float*)d_in[0];   // [32,512,512] f32
    const int*   dur = (const int*)d_in[1];     // [32,512] i32
    float* out = (float*)d_out;                 // [32*2048*512 + 32] f32

    const int tail = out_size - BB;  // mel_lengths live at the end

    dim3 grid(MAXLEN / ROWS_PER_BLOCK, BB);
    fused_regulate_kernel<<<grid, 256>>>((const float4*)x, (const int2*)dur,
                                         out, tail);
}